// round 7
// baseline (speedup 1.0000x reference)
#include <cuda_runtime.h>
#include <cuda_bf16.h>
#include <math.h>
#include <stdint.h>

typedef unsigned long long ull;

#define NB 16
#define NH 64
#define NL 16384
#define NN 64
#define NCD 32
#define CT 128                // chunk length
#define NCK (NL / CT)         // 128 chunks per (b,h)
#define KDIM 256              // [u(128) | sr(64) | si(64)]

// ---------------- device scratch (statics per harness rules) ----------------
__device__ __nv_bfloat16 g_uhi[(size_t)NB * NH * NL];
__device__ __nv_bfloat16 g_ulo[(size_t)NB * NH * NL];
__device__ float         g_e  [(size_t)NB * NH * NCK * 128];   // chunk-end sums
__device__ __nv_bfloat16 g_shi[(size_t)NB * NH * NCK * 128];   // entry states hi
__device__ __nv_bfloat16 g_slo[(size_t)NB * NH * NCK * 128];   // entry states lo
__device__ __nv_bfloat16 g_Ghi[(size_t)NH * CT * KDIM];        // main B [128 x 256]/head
__device__ __nv_bfloat16 g_Glo[(size_t)NH * CT * KDIM];
__device__ __nv_bfloat16 g_Ehi[(size_t)NH * 128 * CT];         // E B [128 x 128]/head
__device__ __nv_bfloat16 g_Elo[(size_t)NH * 128 * CT];
__device__ float         g_wTr[NH * NN], g_wTi[NH * NN];       // w^CT
__device__ float         g_film[2 * NB * NH];

// ---------------- helpers ----------------
__device__ __forceinline__ ull fma2(ull a, ull b, ull c) {
    ull d; asm("fma.rn.f32x2 %0, %1, %2, %3;" : "=l"(d) : "l"(a), "l"(b), "l"(c)); return d;
}
union F2U { float2 f; ull u; };
__device__ __forceinline__ float2 unpack2(ull v) { F2U t; t.u = v; return t.f; }

__device__ __forceinline__ float gelu_exact(float v) {
    return 0.5f * v * (1.0f + erff(v * 0.7071067811865475f));
}
__device__ __forceinline__ void bsplit(float v, __nv_bfloat16& hi, __nv_bfloat16& lo) {
    hi = __float2bfloat16(v);
    lo = __float2bfloat16(v - __bfloat162float(hi));
}

// warp-level bf16 MMA m16n8k16, fp32 accumulate in place
__device__ __forceinline__ void mma16816(float* d, const uint32_t* a,
                                         uint32_t b0, uint32_t b1) {
    asm volatile(
        "mma.sync.aligned.m16n8k16.row.col.f32.bf16.bf16.f32 "
        "{%0,%1,%2,%3}, {%4,%5,%6,%7}, {%8,%9}, {%0,%1,%2,%3};"
        : "+f"(d[0]), "+f"(d[1]), "+f"(d[2]), "+f"(d[3])
        : "r"(a[0]), "r"(a[1]), "r"(a[2]), "r"(a[3]), "r"(b0), "r"(b1));
}

// A fragment (m16k16, row-major) from memory: row/ld/col in elements
__device__ __forceinline__ void load_afrag(uint32_t* a, const __nv_bfloat16* base,
                                           int row, int ld, int col) {
    a[0] = *(const uint32_t*)(base + (size_t)row * ld + col);
    a[1] = *(const uint32_t*)(base + (size_t)(row + 8) * ld + col);
    a[2] = *(const uint32_t*)(base + (size_t)row * ld + col + 8);
    a[3] = *(const uint32_t*)(base + (size_t)(row + 8) * ld + col + 8);
}

// w = exp(dt*A), c = 2*C*(w-1)/A for this lane's two states
__device__ __forceinline__ void lane_wc(int h, int lane,
                                        const float* __restrict__ log_dt,
                                        const float* __restrict__ log_A_real,
                                        const float* __restrict__ A_imag,
                                        const float* __restrict__ C_re,
                                        const float* __restrict__ C_im,
                                        float wr[2], float wi[2],
                                        float cr[2], float ci[2])
{
    const float dt = expf(log_dt[h]);
    #pragma unroll
    for (int s = 0; s < 2; s++) {
        int n = 2 * lane + s;
        float Ar = -expf(log_A_real[h * NN + n]);
        float Ai = A_imag[h * NN + n];
        float er = expf(Ar * dt);
        float sn, cs;
        sincosf(Ai * dt, &sn, &cs);
        wr[s] = er * cs; wi[s] = er * sn;
        float Er = wr[s] - 1.0f, Ei = wi[s];
        float inv = 1.0f / (Ar * Ar + Ai * Ai);
        float Fr = (Er * Ar + Ei * Ai) * inv;
        float Fi = (Ei * Ar - Er * Ai) * inv;
        float Cr = C_re[h * NN + n], Ci = C_im[h * NN + n];
        cr[s] = 2.0f * (Cr * Fr - Ci * Fi);
        ci[s] = 2.0f * (Cr * Fi + Ci * Fr);
    }
}

// =====================================================================
// Kernel 1: premix  u = gelu(W x + b) -> bf16 hi/lo
// =====================================================================
__global__ __launch_bounds__(256, 2) void premix_kernel(
    const float* __restrict__ x, const float* __restrict__ W,
    const float* __restrict__ b_lin)
{
    extern __shared__ float2 sm2[];
    float2* xs = sm2;
    float2* wd = sm2 + NH * 128;

    const int tid = threadIdx.x;
    const int b   = blockIdx.y;
    const int l0  = blockIdx.x * 256;

    for (int i = tid; i < NH * NH; i += 256) {
        float wv = W[i];
        wd[i] = make_float2(wv, wv);
    }
    const float* xb = x + ((size_t)b * NH) * NL + l0;
    for (int i = tid; i < NH * 128; i += 256) {
        int h = i >> 7, p = i & 127;
        xs[i] = *(const float2*)(xb + (size_t)h * NL + 2 * p);
    }
    __syncthreads();

    const int tg   = tid >> 5;
    const int lane = tid & 31;

    ull acc[8][4];
    #pragma unroll
    for (int j = 0; j < 8; j++)
        #pragma unroll
        for (int p = 0; p < 4; p++) acc[j][p] = 0ULL;

    #pragma unroll 4
    for (int h = 0; h < NH; h++) {
        ull xp[4];
        #pragma unroll
        for (int p = 0; p < 4; p++)
            xp[p] = *(const ull*)&xs[h * 128 + lane + 32 * p];
        #pragma unroll
        for (int j = 0; j < 8; j++) {
            ull wv = *(const ull*)&wd[(tg * 8 + j) * NH + h];
            #pragma unroll
            for (int p = 0; p < 4; p++) acc[j][p] = fma2(wv, xp[p], acc[j][p]);
        }
    }

    #pragma unroll
    for (int j = 0; j < 8; j++) {
        int g = tg * 8 + j;
        float bl = b_lin[g];
        size_t base = ((size_t)b * NH + g) * NL + l0;
        __nv_bfloat162* uh = (__nv_bfloat162*)(g_uhi + base);
        __nv_bfloat162* ul = (__nv_bfloat162*)(g_ulo + base);
        #pragma unroll
        for (int p = 0; p < 4; p++) {
            float2 v = unpack2(acc[j][p]);
            float a0 = gelu_exact(v.x + bl), a1 = gelu_exact(v.y + bl);
            __nv_bfloat162 hh, ll;
            bsplit(a0, hh.x, ll.x);
            bsplit(a1, hh.y, ll.y);
            uh[lane + 32 * p] = hh;
            ul[lane + 32 * p] = ll;
        }
    }
}

// =====================================================================
// Kernel 2: per-head constants (G, E, w^CT, FiLM). One warp per head.
// =====================================================================
__global__ __launch_bounds__(128) void consts_kernel(
    const float* __restrict__ log_dt, const float* __restrict__ log_A_real,
    const float* __restrict__ A_imag, const float* __restrict__ C_re,
    const float* __restrict__ C_im,   const float* __restrict__ Dvec,
    const float* __restrict__ cond,   const float* __restrict__ film_W,
    const float* __restrict__ film_b)
{
    __shared__ float Ks[4][CT];
    const int w    = threadIdx.x >> 5;
    const int lane = threadIdx.x & 31;
    const int h    = blockIdx.x * 4 + w;
    const int n0   = 2 * lane, n1 = 2 * lane + 1;

    float wr[2], wi[2], cr[2], ci[2];
    lane_wc(h, lane, log_dt, log_A_real, A_imag, C_re, C_im, wr, wi, cr, ci);

    // K taps: K[m] = sum_n Re(c_n w_n^m), m = 0..CT-1
    {
        float pr[2] = {cr[0], cr[1]}, pi[2] = {ci[0], ci[1]};
        for (int m = 0; m < CT; m++) {
            float v = pr[0] + pr[1];
            #pragma unroll
            for (int o = 16; o > 0; o >>= 1) v += __shfl_xor_sync(0xffffffffu, v, o);
            if (lane == 0) Ks[w][m] = v;
            #pragma unroll
            for (int s = 0; s < 2; s++) {
                float nr = pr[s] * wr[s] - pi[s] * wi[s];
                pi[s] = pr[s] * wi[s] + pi[s] * wr[s];
                pr[s] = nr;
            }
        }
    }
    __syncwarp();
    const float Dh = Dvec[h];

    // G Toeplitz block (cols 0..CT-1), D folded into diagonal
    for (int t = 0; t < CT; t++) {
        size_t row = (size_t)h * CT * KDIM + (size_t)t * KDIM;
        #pragma unroll
        for (int kk = 0; kk < 4; kk++) {
            int k = lane + 32 * kk;
            float val = (k <= t) ? (Ks[w][t - k] + (k == t ? Dh : 0.0f)) : 0.0f;
            bsplit(val, g_Ghi[row + k], g_Glo[row + k]);
        }
    }

    // correction cols: p = c*w^{t+1} -> cols [CT..CT+63]=Re, [CT+64..]= -Im
    {
        float pr[2], pi[2];
        #pragma unroll
        for (int s = 0; s < 2; s++) {
            pr[s] = cr[s] * wr[s] - ci[s] * wi[s];
            pi[s] = cr[s] * wi[s] + ci[s] * wr[s];
        }
        for (int t = 0; t < CT; t++) {
            size_t row = (size_t)h * CT * KDIM + (size_t)t * KDIM;
            bsplit( pr[0], g_Ghi[row + CT + n0],      g_Glo[row + CT + n0]);
            bsplit( pr[1], g_Ghi[row + CT + n1],      g_Glo[row + CT + n1]);
            bsplit(-pi[0], g_Ghi[row + CT + 64 + n0], g_Glo[row + CT + 64 + n0]);
            bsplit(-pi[1], g_Ghi[row + CT + 64 + n1], g_Glo[row + CT + 64 + n1]);
            #pragma unroll
            for (int s = 0; s < 2; s++) {
                float nr = pr[s] * wr[s] - pi[s] * wi[s];
                pi[s] = pr[s] * wi[s] + pi[s] * wr[s];
                pr[s] = nr;
            }
        }
    }

    // E matrix: rows n (Re), 64+n (Im); E[n][k] = w^{CT-1-k}
    {
        float qr[2] = {1.0f, 1.0f}, qi[2] = {0.0f, 0.0f};
        for (int k = CT - 1; k >= 0; k--) {
            size_t base = (size_t)h * 128 * CT;
            bsplit(qr[0], g_Ehi[base + (size_t)n0 * CT + k],        g_Elo[base + (size_t)n0 * CT + k]);
            bsplit(qr[1], g_Ehi[base + (size_t)n1 * CT + k],        g_Elo[base + (size_t)n1 * CT + k]);
            bsplit(qi[0], g_Ehi[base + (size_t)(64 + n0) * CT + k], g_Elo[base + (size_t)(64 + n0) * CT + k]);
            bsplit(qi[1], g_Ehi[base + (size_t)(64 + n1) * CT + k], g_Elo[base + (size_t)(64 + n1) * CT + k]);
            #pragma unroll
            for (int s = 0; s < 2; s++) {
                float nr = qr[s] * wr[s] - qi[s] * wi[s];
                qi[s] = qr[s] * wi[s] + qi[s] * wr[s];
                qr[s] = nr;
            }
        }
    }

    // w^CT via 7 squarings (CT = 2^7)
    {
        float tr[2] = {wr[0], wr[1]}, ti[2] = {wi[0], wi[1]};
        for (int k = 0; k < 7; k++) {
            #pragma unroll
            for (int s = 0; s < 2; s++) {
                float nr = tr[s] * tr[s] - ti[s] * ti[s];
                ti[s] = 2.0f * tr[s] * ti[s];
                tr[s] = nr;
            }
        }
        g_wTr[h * NN + n0] = tr[0]; g_wTr[h * NN + n1] = tr[1];
        g_wTi[h * NN + n0] = ti[0]; g_wTi[h * NN + n1] = ti[1];
    }

    // FiLM per (b,h)
    for (int b = 0; b < NB; b++) {
        float cv = cond[b * NCD + lane];
        float gv = cv * film_W[h * NCD + lane];
        float bv = cv * film_W[(NH + h) * NCD + lane];
        #pragma unroll
        for (int o = 16; o > 0; o >>= 1) {
            gv += __shfl_xor_sync(0xffffffffu, gv, o);
            bv += __shfl_xor_sync(0xffffffffu, bv, o);
        }
        if (lane == 0) {
            g_film[b * NH + h]           = gv + film_b[h];
            g_film[NB * NH + b * NH + h] = bv + film_b[NH + h];
        }
    }
}

// =====================================================================
// Kernel 3: E-GEMM  e[chunk][0..127] = E_h[128x128] . u_chunk
// grid: 2048 CTAs (bh x 2 chunk-halves), 256 threads (8 warps).
// warp = mt(4) x nhalf(2): m16 chunk-rows x n64 outputs, K=128 x3 splits.
// =====================================================================
#define E_PAD 136

__global__ __launch_bounds__(256, 1) void egemm_kernel()
{
    extern __shared__ __nv_bfloat16 esm[];
    __nv_bfloat16* Eh = esm;                 // [128][E_PAD]
    __nv_bfloat16* El = esm + 128 * E_PAD;

    const int tid  = threadIdx.x;
    const int warp = tid >> 5;
    const int lane = tid & 31;
    const int g    = lane >> 2;
    const int cq   = lane & 3;

    const int bh   = blockIdx.x >> 1;
    const int half = blockIdx.x & 1;
    const int h    = bh & 63;
    const int c0   = half * (NCK / 2);       // 64 chunks per CTA

    // stage E hi/lo (128 rows x 128 cols), pad E_PAD
    {
        const uint4* srcH = (const uint4*)(g_Ehi + (size_t)h * 128 * CT);
        const uint4* srcL = (const uint4*)(g_Elo + (size_t)h * 128 * CT);
        for (int i = tid; i < 2048; i += 256) {
            int row = i >> 4, v = i & 15;
            *(uint4*)&Eh[row * E_PAD + v * 8] = srcH[i];
            *(uint4*)&El[row * E_PAD + v * 8] = srcL[i];
        }
    }
    __syncthreads();

    const int mt    = warp & 3;
    const int nbase = (warp >> 2) * 64;
    const int m0    = mt * 16;

    float acc[8][4];
    #pragma unroll
    for (int nt = 0; nt < 8; nt++)
        #pragma unroll
        for (int q = 0; q < 4; q++) acc[nt][q] = 0.0f;

    const __nv_bfloat16* uH = g_uhi + (size_t)bh * NL + (size_t)c0 * CT;
    const __nv_bfloat16* uL = g_ulo + (size_t)bh * NL + (size_t)c0 * CT;
    const __nv_bfloat16* Ap[3] = {uH, uH, uL};
    const __nv_bfloat16* Bp[3] = {Eh, El, Eh};

    #pragma unroll
    for (int sp = 0; sp < 3; sp++) {
        #pragma unroll
        for (int kt = 0; kt < 8; kt++) {
            uint32_t a[4];
            load_afrag(a, Ap[sp], m0 + g, CT, kt * 16 + 2 * cq);
            #pragma unroll
            for (int nt = 0; nt < 8; nt++) {
                const __nv_bfloat16* Brow = Bp[sp] + (nbase + nt * 8 + g) * E_PAD + kt * 16 + 2 * cq;
                uint32_t b0 = *(const uint32_t*)Brow;
                uint32_t b1 = *(const uint32_t*)(Brow + 8);
                mma16816(acc[nt], a, b0, b1);
            }
        }
    }

    float* eb = g_e + ((size_t)bh * NCK + c0) * 128;
    #pragma unroll
    for (int nt = 0; nt < 8; nt++) {
        int col = nbase + nt * 8 + 2 * cq;
        *(float2*)&eb[(size_t)(m0 + g) * 128 + col]     = make_float2(acc[nt][0], acc[nt][1]);
        *(float2*)&eb[(size_t)(m0 + g + 8) * 128 + col] = make_float2(acc[nt][2], acc[nt][3]);
    }
}

// =====================================================================
// Kernel 4: inter-chunk scan; writes entry states s hi/lo bf16.
// One warp per (b,h).  s_{c+1} = w^CT * s_c + e_c, s_0 = 0.
// =====================================================================
__global__ __launch_bounds__(128) void chunk_scan_kernel()
{
    const int w    = threadIdx.x >> 5;
    const int lane = threadIdx.x & 31;
    const int bh   = blockIdx.x * 4 + w;
    const int h    = bh & 63;
    const int n0   = 2 * lane, n1 = n0 + 1;

    const float wTr0 = g_wTr[h * NN + n0], wTi0 = g_wTi[h * NN + n0];
    const float wTr1 = g_wTr[h * NN + n1], wTi1 = g_wTi[h * NN + n1];

    float sr0 = 0.f, si0 = 0.f, sr1 = 0.f, si1 = 0.f;

    const float2* ep = (const float2*)g_e;
    float2 erb[4], eib[4];
    #pragma unroll
    for (int j = 0; j < 4; j++) {
        size_t o = ((size_t)bh * NCK + j) * 64;
        erb[j] = ep[o + lane];
        eib[j] = ep[o + 32 + lane];
    }

    #pragma unroll 4
    for (int c = 0; c < NCK; c++) {
        const int sl = c & 3;

        size_t sb = ((size_t)bh * NCK + c) * 128;
        __nv_bfloat162 hre, lre, him, lim;
        bsplit(sr0, hre.x, lre.x); bsplit(sr1, hre.y, lre.y);
        bsplit(si0, him.x, lim.x); bsplit(si1, him.y, lim.y);
        ((__nv_bfloat162*)(g_shi + sb))[lane]      = hre;
        ((__nv_bfloat162*)(g_shi + sb))[32 + lane] = him;
        ((__nv_bfloat162*)(g_slo + sb))[lane]      = lre;
        ((__nv_bfloat162*)(g_slo + sb))[32 + lane] = lim;

        float2 er = erb[sl], ei = eib[sl];
        if (c + 4 < NCK) {
            size_t o = ((size_t)bh * NCK + c + 4) * 64;
            erb[sl] = ep[o + lane];
            eib[sl] = ep[o + 32 + lane];
        }

        float nr0 = wTr0 * sr0 - wTi0 * si0 + er.x;
        float ni0 = wTr0 * si0 + wTi0 * sr0 + ei.x;
        float nr1 = wTr1 * sr1 - wTi1 * si1 + er.y;
        float ni1 = wTr1 * si1 + wTi1 * sr1 + ei.y;
        sr0 = nr0; si0 = ni0; sr1 = nr1; si1 = ni1;
    }
}

// =====================================================================
// Kernel 5: main GEMM  y[chunk][t] = G_h[128x256] . [u|sr|si]
// + fused FiLM + GELU + residual epilogue.
// grid: 2048 CTAs (bh x 2 chunk-halves), 256 threads (8 warps).
// warp = mt(4) x nhalf(2): m16 chunks x n64 positions, K=256 x3 splits.
// =====================================================================
#define G_PAD 264

__global__ __launch_bounds__(256, 1) void maingemm_kernel(
    const float* __restrict__ x, const float* __restrict__ res_w,
    float* __restrict__ out)
{
    extern __shared__ __nv_bfloat16 gsm[];
    __nv_bfloat16* Gh = gsm;                 // [128][G_PAD]
    __nv_bfloat16* Gl = gsm + 128 * G_PAD;

    const int tid  = threadIdx.x;
    const int warp = tid >> 5;
    const int lane = tid & 31;
    const int g    = lane >> 2;
    const int cq   = lane & 3;

    const int bh   = blockIdx.x >> 1;
    const int half = blockIdx.x & 1;
    const int h    = bh & 63;
    const int c0   = half * (NCK / 2);       // 64 chunks per CTA

    // stage G hi/lo (128 rows x 256 cols), pad G_PAD
    {
        const uint4* srcH = (const uint4*)(g_Ghi + (size_t)h * CT * KDIM);
        const uint4* srcL = (const uint4*)(g_Glo + (size_t)h * CT * KDIM);
        for (int i = tid; i < 4096; i += 256) {
            int row = i >> 5, v = i & 31;
            *(uint4*)&Gh[row * G_PAD + v * 8] = srcH[i];
            *(uint4*)&Gl[row * G_PAD + v * 8] = srcL[i];
        }
    }
    __syncthreads();

    const int mt    = warp & 3;
    const int nbase = (warp >> 2) * 64;
    const int m0    = mt * 16;

    float acc[8][4];
    #pragma unroll
    for (int nt = 0; nt < 8; nt++)
        #pragma unroll
        for (int q = 0; q < 4; q++) acc[nt][q] = 0.0f;

    const __nv_bfloat16* uH = g_uhi + (size_t)bh * NL + (size_t)c0 * CT;
    const __nv_bfloat16* uL = g_ulo + (size_t)bh * NL + (size_t)c0 * CT;
    const __nv_bfloat16* sH = g_shi + ((size_t)bh * NCK + c0) * 128;
    const __nv_bfloat16* sL = g_slo + ((size_t)bh * NCK + c0) * 128;
    const __nv_bfloat16* Au[3] = {uH, uH, uL};
    const __nv_bfloat16* As[3] = {sH, sH, sL};
    const __nv_bfloat16* Bp[3] = {Gh, Gl, Gh};

    #pragma unroll
    for (int sp = 0; sp < 3; sp++) {
        #pragma unroll
        for (int kt = 0; kt < 16; kt++) {
            uint32_t a[4];
            if (kt < 8) {
                load_afrag(a, Au[sp], m0 + g, CT, kt * 16 + 2 * cq);
            } else {
                load_afrag(a, As[sp], m0 + g, 128, (kt - 8) * 16 + 2 * cq);
            }
            #pragma unroll
            for (int nt = 0; nt < 8; nt++) {
                const __nv_bfloat16* Brow = Bp[sp] + (nbase + nt * 8 + g) * G_PAD + kt * 16 + 2 * cq;
                uint32_t b0 = *(const uint32_t*)Brow;
                uint32_t b1 = *(const uint32_t*)(Brow + 8);
                mma16816(acc[nt], a, b0, b1);
            }
        }
    }

    // ---- epilogue: FiLM + gelu + residual ----
    const float gv  = g_film[bh];
    const float bv  = g_film[NB * NH + bh];
    const float rwv = res_w[h];
    const size_t lb = (size_t)bh * NL + (size_t)c0 * CT;

    #pragma unroll
    for (int nt = 0; nt < 8; nt++) {
        int col = nbase + nt * 8 + 2 * cq;
        size_t l0 = lb + (size_t)(m0 + g) * CT + col;
        size_t l1 = lb + (size_t)(m0 + g + 8) * CT + col;
        float2 x0 = *(const float2*)(x + l0);
        float2 x1 = *(const float2*)(x + l1);
        float2 o0, o1;
        o0.x = gelu_exact(acc[nt][0] * gv + bv) + x0.x * rwv;
        o0.y = gelu_exact(acc[nt][1] * gv + bv) + x0.y * rwv;
        o1.x = gelu_exact(acc[nt][2] * gv + bv) + x1.x * rwv;
        o1.y = gelu_exact(acc[nt][3] * gv + bv) + x1.y * rwv;
        *(float2*)(out + l0) = o0;
        *(float2*)(out + l1) = o1;
    }
}

// =====================================================================
extern "C" void kernel_launch(void* const* d_in, const int* in_sizes, int n_in,
                              void* d_out, int out_size)
{
    (void)in_sizes; (void)n_in; (void)out_size;
    const float* x      = (const float*)d_in[0];
    const float* cond   = (const float*)d_in[1];
    const float* W      = (const float*)d_in[2];
    const float* b_lin  = (const float*)d_in[3];
    const float* log_dt = (const float*)d_in[4];
    const float* lAr    = (const float*)d_in[5];
    const float* Aim    = (const float*)d_in[6];
    const float* Cre    = (const float*)d_in[7];
    const float* Cim    = (const float*)d_in[8];
    const float* Dv     = (const float*)d_in[9];
    const float* fW     = (const float*)d_in[10];
    const float* fb     = (const float*)d_in[11];
    const float* rw     = (const float*)d_in[12];
    float* out = (float*)d_out;

    const int e_smem = 2 * 128 * E_PAD * 2;      // 69632 B
    const int g_smem = 2 * 128 * G_PAD * 2;      // 135168 B

    cudaFuncSetAttribute(premix_kernel,
                         cudaFuncAttributeMaxDynamicSharedMemorySize, 98304);
    cudaFuncSetAttribute(egemm_kernel,
                         cudaFuncAttributeMaxDynamicSharedMemorySize, e_smem);
    cudaFuncSetAttribute(maingemm_kernel,
                         cudaFuncAttributeMaxDynamicSharedMemorySize, g_smem);

    consts_kernel<<<NH / 4, 128>>>(log_dt, lAr, Aim, Cre, Cim, Dv, cond, fW, fb);
    premix_kernel<<<dim3(NL / 256, NB), 256, 98304>>>(x, W, b_lin);
    egemm_kernel<<<NB * NH * 2, 256, e_smem>>>();
    chunk_scan_kernel<<<(NB * NH) / 4, 128>>>();
    maingemm_kernel<<<NB * NH * 2, 256, g_smem>>>(x, rw, out);
}

// round 8
// speedup vs baseline: 1.2420x; 1.2420x over previous
#include <cuda_runtime.h>
#include <math.h>

typedef unsigned long long ull;

#define NB 16
#define NH 64
#define NL 16384
#define NN 64
#define NCD 32
#define NC 8          // chunks per sequence
#define CLEN 2048     // NL / NC

// scratch (static __device__ per harness rules)
__device__ float g_u[(size_t)NB * NH * NL];            // premixed+gelu input
__device__ ull   g_e[(size_t)NB * NH * (NC - 1) * 64]; // chunk end states (packed f32x2)
__device__ ull   g_s[(size_t)NB * NH * NC * 64];       // entering states

// ---------- packed f32x2 helpers ----------
__device__ __forceinline__ ull fma2(ull a, ull b, ull c) {
    ull d;
    asm("fma.rn.f32x2 %0, %1, %2, %3;" : "=l"(d) : "l"(a), "l"(b), "l"(c));
    return d;
}
__device__ __forceinline__ ull mul2(ull a, ull b) {
    ull d;
    asm("mul.rn.f32x2 %0, %1, %2;" : "=l"(d) : "l"(a), "l"(b));
    return d;
}
__device__ __forceinline__ ull add2(ull a, ull b) {
    ull d;
    asm("add.rn.f32x2 %0, %1, %2;" : "=l"(d) : "l"(a), "l"(b));
    return d;
}
union F2U { float2 f; ull u; };
__device__ __forceinline__ ull pack2(float a, float b) { F2U t; t.f = make_float2(a, b); return t.u; }
__device__ __forceinline__ float2 unpack2(ull v) { F2U t; t.u = v; return t.f; }

__device__ __forceinline__ float gelu_exact(float v) {
    return 0.5f * v * (1.0f + erff(v * 0.7071067811865475f));
}

// w = exp(dt*A) for the two states this lane owns
__device__ __forceinline__ void lane_w(int h, int lane,
                                       const float* __restrict__ log_dt,
                                       const float* __restrict__ log_A_real,
                                       const float* __restrict__ A_imag,
                                       float wr[2], float wi[2])
{
    const float dt = expf(log_dt[h]);
    #pragma unroll
    for (int s = 0; s < 2; s++) {
        int n = 2 * lane + s;
        float Ar = -expf(log_A_real[h * NN + n]);
        float Ai = A_imag[h * NN + n];
        float er = expf(Ar * dt);
        float sn, cs;
        sincosf(Ai * dt, &sn, &cs);
        wr[s] = er * cs;
        wi[s] = er * sn;
    }
}

// =====================================================================
// Kernel 1: premix  u = gelu(W x + b)
// =====================================================================
__global__ __launch_bounds__(256, 2) void premix_kernel(
    const float* __restrict__ x, const float* __restrict__ W,
    const float* __restrict__ b_lin)
{
    extern __shared__ float2 sm2[];
    float2* xs = sm2;            // [NH][128]
    float2* wd = sm2 + NH * 128; // [NH][NH]

    const int tid = threadIdx.x;
    const int b   = blockIdx.y;
    const int l0  = blockIdx.x * 256;

    for (int i = tid; i < NH * NH; i += 256) {
        float wv = W[i];
        wd[i] = make_float2(wv, wv);
    }
    const float* xb = x + ((size_t)b * NH) * NL + l0;
    for (int i = tid; i < NH * 128; i += 256) {
        int h = i >> 7, p = i & 127;
        xs[i] = *(const float2*)(xb + (size_t)h * NL + 2 * p);
    }
    __syncthreads();

    const int tg   = tid >> 5;
    const int lane = tid & 31;

    ull acc[8][4];
    #pragma unroll
    for (int j = 0; j < 8; j++)
        #pragma unroll
        for (int p = 0; p < 4; p++) acc[j][p] = 0ULL;

    #pragma unroll 4
    for (int h = 0; h < NH; h++) {
        ull xp[4];
        #pragma unroll
        for (int p = 0; p < 4; p++)
            xp[p] = *(const ull*)&xs[h * 128 + lane + 32 * p];
        #pragma unroll
        for (int j = 0; j < 8; j++) {
            ull wv = *(const ull*)&wd[(tg * 8 + j) * NH + h];
            #pragma unroll
            for (int p = 0; p < 4; p++) acc[j][p] = fma2(wv, xp[p], acc[j][p]);
        }
    }

    #pragma unroll
    for (int j = 0; j < 8; j++) {
        int g = tg * 8 + j;
        float bl = b_lin[g];
        float2* ub = (float2*)(g_u + ((size_t)b * NH + g) * NL + l0);
        #pragma unroll
        for (int p = 0; p < 4; p++) {
            float2 v = unpack2(acc[j][p]);
            ub[lane + 32 * p] = make_float2(gelu_exact(v.x + bl), gelu_exact(v.y + bl));
        }
    }
}

// =====================================================================
// Kernel 2: pass 1 — zero-init state recurrence per chunk (chunks 0..NC-2)
// 8-step grouped:  q' = w^8 q + (w^7 u1 + ... + w u7 + u8)
// =====================================================================
__global__ __launch_bounds__(128) void state_kernel(
    const float* __restrict__ log_dt, const float* __restrict__ log_A_real,
    const float* __restrict__ A_imag)
{
    __shared__ __align__(16) float2 Us[4][2][32];

    const int w    = threadIdx.x >> 5;
    const int lane = threadIdx.x & 31;
    const int idx  = blockIdx.x * 4 + w;
    const int bh   = idx / (NC - 1);
    const int c    = idx - bh * (NC - 1);
    const int h    = bh & 63;

    float wr[2], wi[2];
    lane_w(h, lane, log_dt, log_A_real, A_imag, wr, wi);

    // w^1..w^8 per lane-state
    float pr[8][2], pi[8][2];
    #pragma unroll
    for (int s = 0; s < 2; s++) { pr[0][s] = wr[s]; pi[0][s] = wi[s]; }
    #pragma unroll
    for (int k = 1; k < 8; k++) {
        #pragma unroll
        for (int s = 0; s < 2; s++) {
            pr[k][s] = pr[k-1][s] * wr[s] - pi[k-1][s] * wi[s];
            pi[k][s] = pr[k-1][s] * wi[s] + pi[k-1][s] * wr[s];
        }
    }
    const ull w1r2 = pack2(pr[0][0], pr[0][1]), w1i2 = pack2(pi[0][0], pi[0][1]);
    const ull w2r2 = pack2(pr[1][0], pr[1][1]), w2i2 = pack2(pi[1][0], pi[1][1]);
    const ull w3r2 = pack2(pr[2][0], pr[2][1]), w3i2 = pack2(pi[2][0], pi[2][1]);
    const ull w4r2 = pack2(pr[3][0], pr[3][1]), w4i2 = pack2(pi[3][0], pi[3][1]);
    const ull w5r2 = pack2(pr[4][0], pr[4][1]), w5i2 = pack2(pi[4][0], pi[4][1]);
    const ull w6r2 = pack2(pr[5][0], pr[5][1]), w6i2 = pack2(pi[5][0], pi[5][1]);
    const ull w7r2 = pack2(pr[6][0], pr[6][1]), w7i2 = pack2(pi[6][0], pi[6][1]);
    const ull w8r2 = pack2(pr[7][0], pr[7][1]), w8i2 = pack2(pi[7][0], pi[7][1]);
    const ull nw8i2 = pack2(-pi[7][0], -pi[7][1]);

    const float* ub = g_u + (size_t)bh * NL + (size_t)c * CLEN;

    float u_cur = ub[lane];
    ull qr = 0ULL, qi = 0ULL;

    for (int l0 = 0; l0 < CLEN; l0 += 32) {
        float2* U = Us[w][(l0 >> 5) & 1];
        U[lane] = make_float2(u_cur, u_cur);
        int nn = (l0 + 32 < CLEN) ? (l0 + 32 + lane) : lane;
        float u_nx = ub[nn];
        __syncwarp();
        #pragma unroll
        for (int m = 0; m < 4; m++) {
            ulonglong2 p01 = *(const ulonglong2*)&U[8*m];
            ulonglong2 p23 = *(const ulonglong2*)&U[8*m + 2];
            ulonglong2 p45 = *(const ulonglong2*)&U[8*m + 4];
            ulonglong2 p67 = *(const ulonglong2*)&U[8*m + 6];
            ull rr = fma2(w7r2, p01.x, fma2(w6r2, p01.y, fma2(w5r2, p23.x,
                     fma2(w4r2, p23.y, fma2(w3r2, p45.x, fma2(w2r2, p45.y,
                     fma2(w1r2, p67.x, p67.y)))))));
            ull ri = fma2(w7i2, p01.x, fma2(w6i2, p01.y, fma2(w5i2, p23.x,
                     fma2(w4i2, p23.y, fma2(w3i2, p45.x, fma2(w2i2, p45.y,
                     mul2(w1i2, p67.x)))))));
            ull nqr = fma2(w8r2, qr, fma2(nw8i2, qi, rr));
            qi      = fma2(w8i2, qr, fma2(w8r2,  qi, ri));
            qr      = nqr;
        }
        u_cur = u_nx;
    }

    ull* ep = g_e + ((size_t)(bh * (NC - 1) + c)) * 64;
    ep[lane]      = qr;
    ep[lane + 32] = qi;
}

// =====================================================================
// Kernel 3: pass 2 — serial combine over chunks (tiny)
// =====================================================================
__global__ __launch_bounds__(128) void combine_kernel(
    const float* __restrict__ log_dt, const float* __restrict__ log_A_real,
    const float* __restrict__ A_imag)
{
    const int w    = threadIdx.x >> 5;
    const int lane = threadIdx.x & 31;
    const int bh   = blockIdx.x * 4 + w;
    const int h    = bh & 63;

    float wr[2], wi[2];
    lane_w(h, lane, log_dt, log_A_real, A_imag, wr, wi);

    float tr[2] = {wr[0], wr[1]}, ti[2] = {wi[0], wi[1]};
    for (int k = 0; k < 11; k++) {
        #pragma unroll
        for (int s = 0; s < 2; s++) {
            float nr = tr[s]*tr[s] - ti[s]*ti[s];
            ti[s] = 2.0f*tr[s]*ti[s];
            tr[s] = nr;
        }
    }

    float sr[2] = {0.f, 0.f}, si[2] = {0.f, 0.f};
    for (int c = 0; c < NC; c++) {
        ull* sp = g_s + ((size_t)(bh * NC + c)) * 64;
        sp[lane]      = pack2(sr[0], sr[1]);
        sp[lane + 32] = pack2(si[0], si[1]);
        if (c < NC - 1) {
            const ull* ep = g_e + ((size_t)(bh * (NC - 1) + c)) * 64;
            float2 er = unpack2(ep[lane]);
            float2 ei = unpack2(ep[lane + 32]);
            float e_r[2] = {er.x, er.y}, e_i[2] = {ei.x, ei.y};
            #pragma unroll
            for (int s = 0; s < 2; s++) {
                float nr = tr[s]*sr[s] - ti[s]*si[s] + e_r[s];
                float ni = tr[s]*si[s] + ti[s]*sr[s] + e_i[s];
                sr[s] = nr; si[s] = ni;
            }
        }
    }
}

// =====================================================================
// Kernel 4: pass 3 — 4-step grouped scan with true entering state,
// packed f32x2 staging (saves per-step pair-sum FADD), interior outputs
// projected off group-entry state + Toeplitz taps, fused FiLM+GELU+res.
// =====================================================================
__global__ __launch_bounds__(128, 5) void scan_kernel(
    const float* __restrict__ x,
    const float* __restrict__ log_dt, const float* __restrict__ log_A_real,
    const float* __restrict__ A_imag, const float* __restrict__ C_re,
    const float* __restrict__ C_im,   const float* __restrict__ Dvec,
    const float* __restrict__ cond,   const float* __restrict__ film_W,
    const float* __restrict__ film_b, const float* __restrict__ res_w,
    float* __restrict__ out)
{
    __shared__ __align__(16) float2 Us[4][2][32];
    __shared__ ull Ps[4][32 * 33];      // packed per-step contributions

    const int w    = threadIdx.x >> 5;
    const int lane = threadIdx.x & 31;
    const int idx  = blockIdx.x * 4 + w;
    const int bh   = idx >> 3;
    const int c    = idx & 7;
    const int b    = bh >> 6;
    const int h    = bh & 63;

    float wr[2], wi[2];
    lane_w(h, lane, log_dt, log_A_real, A_imag, wr, wi);

    // coef c = 2*C*(w-1)/A
    float cr[2], ci[2];
    #pragma unroll
    for (int s = 0; s < 2; s++) {
        int n = 2 * lane + s;
        float Ar = -expf(log_A_real[h * NN + n]);
        float Ai = A_imag[h * NN + n];
        float Er = wr[s] - 1.0f, Ei = wi[s];
        float inv = 1.0f / (Ar*Ar + Ai*Ai);
        float Fr = (Er*Ar + Ei*Ai) * inv;
        float Fi = (Ei*Ar - Er*Ai) * inv;
        float Cr = C_re[h * NN + n], Ci = C_im[h * NN + n];
        cr[s] = 2.0f * (Cr*Fr - Ci*Fi);
        ci[s] = 2.0f * (Cr*Fi + Ci*Fr);
    }

    // w powers and projected coefs c*w^g
    float w2r[2], w2i[2], w3r[2], w3i[2], w4r[2], w4i[2];
    float c1r[2], c1i[2], c2r[2], c2i[2], c3r[2], c3i[2];
    #pragma unroll
    for (int s = 0; s < 2; s++) {
        w2r[s] = wr[s]*wr[s] - wi[s]*wi[s];   w2i[s] = 2.0f*wr[s]*wi[s];
        w3r[s] = w2r[s]*wr[s] - w2i[s]*wi[s]; w3i[s] = w2r[s]*wi[s] + w2i[s]*wr[s];
        w4r[s] = w2r[s]*w2r[s] - w2i[s]*w2i[s]; w4i[s] = 2.0f*w2r[s]*w2i[s];
        c1r[s] = cr[s]*wr[s]  - ci[s]*wi[s];  c1i[s] = cr[s]*wi[s]  + ci[s]*wr[s];
        c2r[s] = cr[s]*w2r[s] - ci[s]*w2i[s]; c2i[s] = cr[s]*w2i[s] + ci[s]*w2r[s];
        c3r[s] = cr[s]*w3r[s] - ci[s]*w3i[s]; c3i[s] = cr[s]*w3i[s] + ci[s]*w3r[s];
    }
    const ull w1r2 = pack2(wr[0], wr[1]),   w1i2 = pack2(wi[0], wi[1]);
    const ull w2r2 = pack2(w2r[0], w2r[1]), w2i2 = pack2(w2i[0], w2i[1]);
    const ull w3r2 = pack2(w3r[0], w3r[1]), w3i2 = pack2(w3i[0], w3i[1]);
    const ull w4r2 = pack2(w4r[0], w4r[1]), w4i2 = pack2(w4i[0], w4i[1]);
    const ull nw4i2 = pack2(-w4i[0], -w4i[1]);
    const ull cr2  = pack2(cr[0], cr[1]),   nci2 = pack2(-ci[0], -ci[1]);
    const ull c1r2 = pack2(c1r[0], c1r[1]), nc1i2 = pack2(-c1i[0], -c1i[1]);
    const ull c2r2 = pack2(c2r[0], c2r[1]), nc2i2 = pack2(-c2i[0], -c2i[1]);
    const ull c3r2 = pack2(c3r[0], c3r[1]), nc3i2 = pack2(-c3i[0], -c3i[1]);

    // Toeplitz taps k_g = sum_n Re(c_n w_n^g), g = 0,1,2
    float k0 = cr[0] + cr[1];
    float k1 = c1r[0] + c1r[1];
    float k2 = c2r[0] + c2r[1];
    #pragma unroll
    for (int o = 16; o > 0; o >>= 1) {
        k0 += __shfl_xor_sync(0xffffffffu, k0, o);
        k1 += __shfl_xor_sync(0xffffffffu, k1, o);
        k2 += __shfl_xor_sync(0xffffffffu, k2, o);
    }

    // FiLM gains
    float cv   = cond[b * NCD + lane];
    float gacc = cv * film_W[h * NCD + lane];
    float bacc = cv * film_W[(NH + h) * NCD + lane];
    #pragma unroll
    for (int o = 16; o > 0; o >>= 1) {
        gacc += __shfl_xor_sync(0xffffffffu, gacc, o);
        bacc += __shfl_xor_sync(0xffffffffu, bacc, o);
    }
    gacc += film_b[h];
    bacc += film_b[NH + h];
    const float Dh = Dvec[h];
    const float rw = res_w[h];

    const size_t base = (size_t)bh * NL + (size_t)c * CLEN;
    const float* ub = g_u + base;
    const float* xb = x + base;
    float*       ob = out + base;

    // entering state  (q_{-1} for this chunk)
    const ull* sp = g_s + ((size_t)(bh * NC + c)) * 64;
    ull qr = sp[lane];
    ull qi = sp[lane + 32];

    float u_cur = ub[lane];
    float x_cur = xb[lane];

    ull* P = Ps[w];
    const int d = lane & 3;

    for (int l0 = 0; l0 < CLEN; l0 += 32) {
        float2* U = Us[w][(l0 >> 5) & 1];
        U[lane] = make_float2(u_cur, u_cur);

        int nn = (l0 + 32 < CLEN) ? (l0 + 32 + lane) : lane;
        float u_nx = ub[nn];
        float x_nx = xb[nn];

        __syncwarp();
        #pragma unroll
        for (int m = 0; m < 8; m++) {
            ulonglong2 p01 = *(const ulonglong2*)&U[4*m];
            ulonglong2 p23 = *(const ulonglong2*)&U[4*m + 2];
            // prep: r = w^3 u1 + w^2 u2 + w u3 + u4
            ull rr = fma2(w3r2, p01.x, fma2(w2r2, p01.y, fma2(w1r2, p23.x, p23.y)));
            ull ri = fma2(w3i2, p01.x, fma2(w2i2, p01.y, mul2(w1i2, p23.x)));
            // interior projections off entry state
            ull P1 = fma2(c1r2, qr, mul2(nc1i2, qi));
            ull P2 = fma2(c2r2, qr, mul2(nc2i2, qi));
            ull P3 = fma2(c3r2, qr, mul2(nc3i2, qi));
            // state update
            ull nqr = fma2(w4r2, qr, fma2(nw4i2, qi, rr));
            qi      = fma2(w4i2, qr, fma2(w4r2,  qi, ri));
            qr      = nqr;
            ull P4  = fma2(cr2, qr, mul2(nci2, qi));
            P[(4*m + 0)*33 + lane] = P1;
            P[(4*m + 1)*33 + lane] = P2;
            P[(4*m + 2)*33 + lane] = P3;
            P[(4*m + 3)*33 + lane] = P4;
        }
        __syncwarp();

        // reduce: thread `lane` handles step l0+lane (packed add2 chains)
        const ull* row = &P[lane * 33];
        ull a0 = 0ULL, a1 = 0ULL, a2 = 0ULL, a3 = 0ULL;
        #pragma unroll
        for (int k = 0; k < 32; k += 4) {
            a0 = add2(a0, row[k]);
            a1 = add2(a1, row[k + 1]);
            a2 = add2(a2, row[k + 2]);
            a3 = add2(a3, row[k + 3]);
        }
        float2 av = unpack2(add2(add2(a0, a1), add2(a2, a3)));
        float ul = U[lane].x;
        float extra = Dh * ul;
        if (d == 0)      extra += k0 * ul;
        else if (d == 1) extra += k0 * ul + k1 * U[lane - 1].x;
        else if (d == 2) extra += k0 * ul + k1 * U[lane - 1].x + k2 * U[lane - 2].x;
        float y = av.x + av.y + extra;
        float o = gelu_exact(y * gacc + bacc) + x_cur * rw;
        ob[l0 + lane] = o;

        __syncwarp();   // protect P (single-buffered) before next tile

        u_cur = u_nx;
        x_cur = x_nx;
    }
}

// =====================================================================
extern "C" void kernel_launch(void* const* d_in, const int* in_sizes, int n_in,
                              void* d_out, int out_size)
{
    (void)in_sizes; (void)n_in; (void)out_size;
    const float* x      = (const float*)d_in[0];
    const float* cond   = (const float*)d_in[1];
    const float* W      = (const float*)d_in[2];
    const float* b_lin  = (const float*)d_in[3];
    const float* log_dt = (const float*)d_in[4];
    const float* lAr    = (const float*)d_in[5];
    const float* Aim    = (const float*)d_in[6];
    const float* Cre    = (const float*)d_in[7];
    const float* Cim    = (const float*)d_in[8];
    const float* Dv     = (const float*)d_in[9];
    const float* fW     = (const float*)d_in[10];
    const float* fb     = (const float*)d_in[11];
    const float* rw     = (const float*)d_in[12];
    float* out = (float*)d_out;

    cudaFuncSetAttribute(premix_kernel,
                         cudaFuncAttributeMaxDynamicSharedMemorySize, 98304);

    premix_kernel<<<dim3(NL / 256, NB), 256, 98304>>>(x, W, b_lin);
    state_kernel<<<(NB * NH * (NC - 1)) / 4, 128>>>(log_dt, lAr, Aim);
    combine_kernel<<<(NB * NH) / 4, 128>>>(log_dt, lAr, Aim);
    scan_kernel<<<(NB * NH * NC) / 4, 128>>>(x, log_dt, lAr, Aim, Cre, Cim,
                                             Dv, cond, fW, fb, rw, out);
}